// round 2
// baseline (speedup 1.0000x reference)
#include <cuda_runtime.h>
#include <cstdint>
#include <cstddef>

// ---------------------------------------------------------------------------
// ViT-B/16 @384, B=8, fp32 forward. Baseline: tiled SGEMM + tiled attention.
// ---------------------------------------------------------------------------

#define NTOK   577
#define DIMM   768
#define NHEAD  12
#define HD     64
#define HID    3072
#define BATCH  8
#define TOKS   (BATCH * NTOK)      // 4616
#define NPATCH 576
#define DEPTH  12

// ---------------- scratch (static device allocations are allowed) ----------
__device__ float g_h[TOKS * DIMM];
__device__ float g_y[TOKS * DIMM];
__device__ float g_qkv[TOKS * 3 * DIMM];
__device__ float g_S[(size_t)BATCH * NHEAD * NTOK * NTOK];   // 128 MB
__device__ float g_att[TOKS * DIMM];
__device__ float g_mlp[(size_t)TOKS * HID];
__device__ float g_patches[BATCH * NPATCH * DIMM];
__device__ float g_hp[BATCH * NPATCH * DIMM];
__device__ float g_pwT[DIMM * DIMM];
__device__ float g_cls[BATCH * DIMM];

// ---------------- patch extraction -----------------------------------------
__global__ void patch_extract(const float* __restrict__ x, float* __restrict__ p) {
    int t = blockIdx.x * blockDim.x + threadIdx.x;
    if (t >= BATCH * NPATCH * DIMM) return;
    int f  = t % DIMM;
    int pr = t / DIMM;
    int b  = pr / NPATCH;
    int i  = pr % NPATCH;
    int gy = i / 24, gx = i % 24;
    int c  = f >> 8;            // f / 256
    int py = (f >> 4) & 15;
    int px = f & 15;
    p[t] = x[((size_t)(b * 3 + c) * 384 + (gy * 16 + py)) * 384 + (gx * 16 + px)];
}

__global__ void transpose_pw(const float* __restrict__ w, float* __restrict__ wt) {
    int t = blockIdx.x * blockDim.x + threadIdx.x;
    if (t >= DIMM * DIMM) return;
    int d = t / DIMM, k = t % DIMM;
    wt[k * DIMM + d] = w[t];
}

__global__ void add_pos_cls(const float* __restrict__ hp, const float* __restrict__ cls,
                            const float* __restrict__ pos, float* __restrict__ h) {
    int t = blockIdx.x;                 // 0..TOKS-1
    int b = t / NTOK, n = t - b * NTOK;
    for (int d = threadIdx.x; d < DIMM; d += blockDim.x) {
        float v = (n == 0) ? cls[d] : hp[(size_t)(b * NPATCH + n - 1) * DIMM + d];
        h[(size_t)t * DIMM + d] = v + pos[n * DIMM + d];
    }
}

// ---------------- LayerNorm (one block = one row of 768) --------------------
__global__ void __launch_bounds__(256) ln_kernel(
    const float* __restrict__ x, const float* __restrict__ g,
    const float* __restrict__ b, float* __restrict__ y,
    float eps, long rstride)
{
    const float* xr = x + (size_t)blockIdx.x * rstride;
    float* yr = y + (size_t)blockIdx.x * DIMM;
    int tid = threadIdx.x;
    float v0 = xr[tid], v1 = xr[tid + 256], v2 = xr[tid + 512];
    float s  = v0 + v1 + v2;
    float sq = v0 * v0 + v1 * v1 + v2 * v2;
    #pragma unroll
    for (int o = 16; o; o >>= 1) {
        s  += __shfl_xor_sync(0xffffffffu, s,  o);
        sq += __shfl_xor_sync(0xffffffffu, sq, o);
    }
    __shared__ float rs[8], rq[8];
    if ((tid & 31) == 0) { rs[tid >> 5] = s; rq[tid >> 5] = sq; }
    __syncthreads();
    if (tid == 0) {
        float ss = 0.f, qq = 0.f;
        #pragma unroll
        for (int i = 0; i < 8; i++) { ss += rs[i]; qq += rq[i]; }
        rs[0] = ss; rq[0] = qq;
    }
    __syncthreads();
    float mean = rs[0] * (1.f / 768.f);
    float var  = rq[0] * (1.f / 768.f) - mean * mean;
    float inv  = rsqrtf(var + eps);
    yr[tid]       = (v0 - mean) * inv * g[tid]       + b[tid];
    yr[tid + 256] = (v1 - mean) * inv * g[tid + 256] + b[tid + 256];
    yr[tid + 512] = (v2 - mean) * inv * g[tid + 512] + b[tid + 512];
}

// ---------------- generic SGEMM: C = A[M,K] @ B[K,N] + bias, epilogue -------
// EPI: 0 = bias only, 1 = bias + exact GELU, 2 = bias + residual add
template <int EPI>
__global__ void __launch_bounds__(256) gemm_kernel(
    const float* __restrict__ A, const float* __restrict__ Bm,
    const float* __restrict__ bias, const float* __restrict__ R,
    float* __restrict__ C, int M, int N, int K)
{
    __shared__ float As[16][132];
    __shared__ float Bs[16][132];
    int tid = threadIdx.x;
    int m0 = blockIdx.y * 128, n0 = blockIdx.x * 128;
    int ty = tid >> 4, tx = tid & 15;
    float acc[8][8] = {};

    for (int k0 = 0; k0 < K; k0 += 16) {
        // A tile: 128 rows x 16 k, stored transposed As[k][m]
        #pragma unroll
        for (int s = 0; s < 2; s++) {
            int idx = tid + s * 256;      // 0..511
            int r = idx >> 2, kq = idx & 3;
            float4 v = make_float4(0.f, 0.f, 0.f, 0.f);
            if (m0 + r < M)
                v = *(const float4*)(A + (size_t)(m0 + r) * K + k0 + kq * 4);
            As[kq * 4 + 0][r] = v.x;
            As[kq * 4 + 1][r] = v.y;
            As[kq * 4 + 2][r] = v.z;
            As[kq * 4 + 3][r] = v.w;
        }
        // B tile: 16 k x 128 n
        #pragma unroll
        for (int s = 0; s < 2; s++) {
            int idx = tid + s * 256;
            int r = idx >> 5, nq = idx & 31;
            float4 v = make_float4(0.f, 0.f, 0.f, 0.f);
            if (n0 + nq * 4 < N)          // N is a multiple of 4 for all calls
                v = *(const float4*)(Bm + (size_t)(k0 + r) * N + n0 + nq * 4);
            *(float4*)&Bs[r][nq * 4] = v;
        }
        __syncthreads();
        #pragma unroll
        for (int kk = 0; kk < 16; kk++) {
            float4 a0 = *(float4*)&As[kk][ty * 8];
            float4 a1 = *(float4*)&As[kk][ty * 8 + 4];
            float4 b0 = *(float4*)&Bs[kk][tx * 8];
            float4 b1 = *(float4*)&Bs[kk][tx * 8 + 4];
            float ar[8] = {a0.x, a0.y, a0.z, a0.w, a1.x, a1.y, a1.z, a1.w};
            float br[8] = {b0.x, b0.y, b0.z, b0.w, b1.x, b1.y, b1.z, b1.w};
            #pragma unroll
            for (int i = 0; i < 8; i++)
                #pragma unroll
                for (int j = 0; j < 8; j++)
                    acc[i][j] = fmaf(ar[i], br[j], acc[i][j]);
        }
        __syncthreads();
    }

    #pragma unroll
    for (int i = 0; i < 8; i++) {
        int m = m0 + ty * 8 + i;
        if (m >= M) continue;
        #pragma unroll
        for (int j = 0; j < 8; j++) {
            int n = n0 + tx * 8 + j;
            if (n >= N) continue;
            float v = acc[i][j] + bias[n];
            if (EPI == 1) v = 0.5f * v * (1.f + erff(v * 0.70710678118654752f));
            if (EPI == 2) v += R[(size_t)m * N + n];
            C[(size_t)m * N + n] = v;
        }
    }
}

// ---------------- attention: S = Q K^T * 1/8  (64x64 tiles) -----------------
__global__ void __launch_bounds__(256) attn_scores(
    const float* __restrict__ qkv, float* __restrict__ S)
{
    int bh = blockIdx.z;
    int b = bh / NHEAD, h = bh - b * NHEAD;
    int q0 = blockIdx.x * 64, k0 = blockIdx.y * 64;
    __shared__ float Qs[64][68], Ks[64][68];
    int tid = threadIdx.x;
    #pragma unroll
    for (int s = 0; s < 4; s++) {
        int idx = tid + s * 256;          // 0..1023
        int r = idx >> 4, c4 = idx & 15;
        int q = q0 + r;
        float4 v = make_float4(0.f, 0.f, 0.f, 0.f);
        if (q < NTOK)
            v = *(const float4*)(qkv + (size_t)(b * NTOK + q) * (3 * DIMM) + h * HD + c4 * 4);
        *(float4*)&Qs[r][c4 * 4] = v;
        int k = k0 + r;
        float4 w = make_float4(0.f, 0.f, 0.f, 0.f);
        if (k < NTOK)
            w = *(const float4*)(qkv + (size_t)(b * NTOK + k) * (3 * DIMM) + DIMM + h * HD + c4 * 4);
        *(float4*)&Ks[r][c4 * 4] = w;
    }
    __syncthreads();
    int ty = tid >> 4, tx = tid & 15;
    float acc[4][4] = {};
    #pragma unroll 8
    for (int d = 0; d < HD; d++) {
        float a[4], bb[4];
        #pragma unroll
        for (int i = 0; i < 4; i++) a[i]  = Qs[ty * 4 + i][d];
        #pragma unroll
        for (int j = 0; j < 4; j++) bb[j] = Ks[tx * 4 + j][d];
        #pragma unroll
        for (int i = 0; i < 4; i++)
            #pragma unroll
            for (int j = 0; j < 4; j++)
                acc[i][j] = fmaf(a[i], bb[j], acc[i][j]);
    }
    #pragma unroll
    for (int i = 0; i < 4; i++) {
        int q = q0 + ty * 4 + i;
        if (q >= NTOK) continue;
        #pragma unroll
        for (int j = 0; j < 4; j++) {
            int k = k0 + tx * 4 + j;
            if (k < NTOK)
                S[((size_t)bh * NTOK + q) * NTOK + k] = acc[i][j] * 0.125f;
        }
    }
}

// ---------------- softmax over rows of 577 ----------------------------------
__global__ void __launch_bounds__(256) softmax_rows(float* __restrict__ S) {
    float* p = S + (size_t)blockIdx.x * NTOK;
    int tid = threadIdx.x;
    bool ok1 = (tid + 256) < NTOK, ok2 = (tid + 512) < NTOK;
    float v0 = p[tid];
    float v1 = ok1 ? p[tid + 256] : -1e30f;
    float v2 = ok2 ? p[tid + 512] : -1e30f;
    float m = fmaxf(fmaxf(v0, v1), v2);
    #pragma unroll
    for (int o = 16; o; o >>= 1) m = fmaxf(m, __shfl_xor_sync(0xffffffffu, m, o));
    __shared__ float red[8];
    if ((tid & 31) == 0) red[tid >> 5] = m;
    __syncthreads();
    if (tid == 0) {
        float mm = red[0];
        #pragma unroll
        for (int i = 1; i < 8; i++) mm = fmaxf(mm, red[i]);
        red[0] = mm;
    }
    __syncthreads();
    m = red[0];
    __syncthreads();
    float e0 = __expf(v0 - m);
    float e1 = ok1 ? __expf(v1 - m) : 0.f;
    float e2 = ok2 ? __expf(v2 - m) : 0.f;
    float s = e0 + e1 + e2;
    #pragma unroll
    for (int o = 16; o; o >>= 1) s += __shfl_xor_sync(0xffffffffu, s, o);
    if ((tid & 31) == 0) red[tid >> 5] = s;
    __syncthreads();
    if (tid == 0) {
        float ss = 0.f;
        #pragma unroll
        for (int i = 0; i < 8; i++) ss += red[i];
        red[0] = ss;
    }
    __syncthreads();
    float inv = 1.f / red[0];
    p[tid] = e0 * inv;
    if (ok1) p[tid + 256] = e1 * inv;
    if (ok2) p[tid + 512] = e2 * inv;
}

// ---------------- O = P @ V  (64q x 64d tile per block) ---------------------
__global__ void __launch_bounds__(256) attn_av(
    const float* __restrict__ S, const float* __restrict__ qkv, float* __restrict__ O)
{
    int bh = blockIdx.y;
    int b = bh / NHEAD, h = bh - b * NHEAD;
    int q0 = blockIdx.x * 64;
    __shared__ float Ps[64][65];
    __shared__ float Vs[64][68];
    int tid = threadIdx.x, ty = tid >> 4, tx = tid & 15;
    float acc[4][4] = {};

    for (int k0 = 0; k0 < NTOK; k0 += 64) {
        #pragma unroll
        for (int s = 0; s < 16; s++) {
            int idx = tid + s * 256;        // 0..4095
            int r = idx >> 6, c = idx & 63;
            float v = 0.f;
            if (q0 + r < NTOK && k0 + c < NTOK)
                v = S[((size_t)bh * NTOK + q0 + r) * NTOK + k0 + c];
            Ps[r][c] = v;
        }
        #pragma unroll
        for (int s = 0; s < 4; s++) {
            int idx = tid + s * 256;
            int r = idx >> 4, c4 = idx & 15;
            float4 v = make_float4(0.f, 0.f, 0.f, 0.f);
            if (k0 + r < NTOK)
                v = *(const float4*)(qkv + (size_t)(b * NTOK + k0 + r) * (3 * DIMM) + 2 * DIMM + h * HD + c4 * 4);
            *(float4*)&Vs[r][c4 * 4] = v;
        }
        __syncthreads();
        #pragma unroll 4
        for (int kk = 0; kk < 64; kk++) {
            float4 vv = *(float4*)&Vs[kk][tx * 4];
            float pr[4];
            #pragma unroll
            for (int i = 0; i < 4; i++) pr[i] = Ps[ty * 4 + i][kk];
            #pragma unroll
            for (int i = 0; i < 4; i++) {
                acc[i][0] = fmaf(pr[i], vv.x, acc[i][0]);
                acc[i][1] = fmaf(pr[i], vv.y, acc[i][1]);
                acc[i][2] = fmaf(pr[i], vv.z, acc[i][2]);
                acc[i][3] = fmaf(pr[i], vv.w, acc[i][3]);
            }
        }
        __syncthreads();
    }
    #pragma unroll
    for (int i = 0; i < 4; i++) {
        int q = q0 + ty * 4 + i;
        if (q >= NTOK) continue;
        #pragma unroll
        for (int j = 0; j < 4; j++)
            O[(size_t)(b * NTOK + q) * DIMM + h * HD + tx * 4 + j] = acc[i][j];
    }
}

// ---------------- host driver ------------------------------------------------
extern "C" void kernel_launch(void* const* d_in, const int* in_sizes, int n_in,
                              void* d_out, int out_size)
{
    const float* x       = (const float*)d_in[0];
    const float* patch_w = (const float*)d_in[1];
    const float* patch_b = (const float*)d_in[2];
    const float* cls_t   = (const float*)d_in[3];
    const float* pos     = (const float*)d_in[4];
    const float* ln1_g   = (const float*)d_in[5];
    const float* ln1_b   = (const float*)d_in[6];
    const float* qkv_w   = (const float*)d_in[7];
    const float* qkv_b   = (const float*)d_in[8];
    const float* proj_w  = (const float*)d_in[9];
    const float* proj_b  = (const float*)d_in[10];
    const float* ln2_g   = (const float*)d_in[11];
    const float* ln2_b   = (const float*)d_in[12];
    const float* w1      = (const float*)d_in[13];
    const float* b1      = (const float*)d_in[14];
    const float* w2      = (const float*)d_in[15];
    const float* b2      = (const float*)d_in[16];
    const float* lnf_g   = (const float*)d_in[17];
    const float* lnf_b   = (const float*)d_in[18];
    const float* head_w  = (const float*)d_in[19];
    const float* head_b  = (const float*)d_in[20];
    float* out = (float*)d_out;

    float *h, *y, *qkv, *S, *att, *mlp, *pat, *hp, *pwT, *cls;
    cudaGetSymbolAddress((void**)&h,   g_h);
    cudaGetSymbolAddress((void**)&y,   g_y);
    cudaGetSymbolAddress((void**)&qkv, g_qkv);
    cudaGetSymbolAddress((void**)&S,   g_S);
    cudaGetSymbolAddress((void**)&att, g_att);
    cudaGetSymbolAddress((void**)&mlp, g_mlp);
    cudaGetSymbolAddress((void**)&pat, g_patches);
    cudaGetSymbolAddress((void**)&hp,  g_hp);
    cudaGetSymbolAddress((void**)&pwT, g_pwT);
    cudaGetSymbolAddress((void**)&cls, g_cls);

    // Patch embed
    patch_extract<<<(BATCH * NPATCH * DIMM + 255) / 256, 256>>>(x, pat);
    transpose_pw<<<(DIMM * DIMM + 255) / 256, 256>>>(patch_w, pwT);
    gemm_kernel<0><<<dim3(6, 36), 256>>>(pat, pwT, patch_b, nullptr, hp,
                                         BATCH * NPATCH, DIMM, DIMM);
    add_pos_cls<<<TOKS, 256>>>(hp, cls_t, pos, h);

    // Transformer blocks
    for (int l = 0; l < DEPTH; l++) {
        ln_kernel<<<TOKS, 256>>>(h, ln1_g + l * DIMM, ln1_b + l * DIMM, y, 1e-5f, DIMM);
        gemm_kernel<0><<<dim3(18, 37), 256>>>(y, qkv_w + (size_t)l * DIMM * 3 * DIMM,
                                              qkv_b + l * 3 * DIMM, nullptr, qkv,
                                              TOKS, 3 * DIMM, DIMM);
        attn_scores<<<dim3(10, 10, BATCH * NHEAD), 256>>>(qkv, S);
        softmax_rows<<<BATCH * NHEAD * NTOK, 256>>>(S);
        attn_av<<<dim3(10, BATCH * NHEAD), 256>>>(S, qkv, att);
        gemm_kernel<2><<<dim3(6, 37), 256>>>(att, proj_w + (size_t)l * DIMM * DIMM,
                                             proj_b + l * DIMM, h, h,
                                             TOKS, DIMM, DIMM);
        ln_kernel<<<TOKS, 256>>>(h, ln2_g + l * DIMM, ln2_b + l * DIMM, y, 1e-5f, DIMM);
        gemm_kernel<1><<<dim3(24, 37), 256>>>(y, w1 + (size_t)l * DIMM * HID,
                                              b1 + l * HID, nullptr, mlp,
                                              TOKS, HID, DIMM);
        gemm_kernel<2><<<dim3(6, 37), 256>>>(mlp, w2 + (size_t)l * HID * DIMM,
                                             b2 + l * DIMM, h, h,
                                             TOKS, DIMM, HID);
    }

    // Final LN on cls tokens only + head
    ln_kernel<<<BATCH, 256>>>(h, lnf_g, lnf_b, cls, 1e-6f, (long)NTOK * DIMM);
    gemm_kernel<0><<<dim3(8, 1), 256>>>(cls, head_w, head_b, nullptr, out,
                                        BATCH, 1000, DIMM);
}

// round 4
// speedup vs baseline: 1.7617x; 1.7617x over previous
#include <cuda_runtime.h>
#include <cuda_bf16.h>
#include <cstdint>
#include <cstddef>

#define NTOK   577
#define DIMM   768
#define NHEAD  12
#define HD     64
#define HID    3072
#define BATCH  8
#define TOKS   (BATCH * NTOK)      // 4616
#define NPATCH 576
#define DEPTH  12

// ======================= asm helpers (sm_80+ only) ==========================
__device__ __forceinline__ uint32_t smem_u32(const void* p) {
    uint32_t a;
    asm("{ .reg .u64 t; cvta.to.shared.u64 t, %1; cvt.u32.u64 %0, t; }" : "=r"(a) : "l"(p));
    return a;
}
__device__ __forceinline__ void cp16(uint32_t s, const void* g, uint32_t sz) {
    asm volatile("cp.async.cg.shared.global [%0], [%1], 16, %2;"
                 :: "r"(s), "l"(g), "r"(sz));
}
__device__ __forceinline__ void ldm_x4(uint32_t addr, uint32_t* r) {
    asm volatile("ldmatrix.sync.aligned.m8n8.x4.shared.b16 {%0,%1,%2,%3}, [%4];"
                 : "=r"(r[0]), "=r"(r[1]), "=r"(r[2]), "=r"(r[3]) : "r"(addr));
}
__device__ __forceinline__ void mma16816(float* c, const uint32_t* a, uint32_t b0, uint32_t b1) {
    asm volatile(
        "mma.sync.aligned.m16n8k16.row.col.f32.bf16.bf16.f32 "
        "{%0,%1,%2,%3}, {%4,%5,%6,%7}, {%8,%9}, {%0,%1,%2,%3};"
        : "+f"(c[0]), "+f"(c[1]), "+f"(c[2]), "+f"(c[3])
        : "r"(a[0]), "r"(a[1]), "r"(a[2]), "r"(a[3]), "r"(b0), "r"(b1));
}

// ======================= scratch ============================================
__device__ float g_h[TOKS * DIMM];
__device__ float g_qkv[TOKS * 3 * DIMM];
__device__ float g_S[(size_t)BATCH * NHEAD * NTOK * NTOK];
__device__ float g_hp[BATCH * NPATCH * DIMM];
__device__ float g_cls[BATCH * DIMM];

__device__ __nv_bfloat16 g_yh[TOKS * DIMM],  g_yl[TOKS * DIMM];
__device__ __nv_bfloat16 g_ath[TOKS * DIMM], g_atl[TOKS * DIMM];
__device__ __nv_bfloat16 g_mh[(size_t)TOKS * HID], g_ml[(size_t)TOKS * HID];
__device__ __nv_bfloat16 g_ph[BATCH * NPATCH * DIMM], g_pl[BATCH * NPATCH * DIMM];
__device__ __nv_bfloat16 g_pwh[DIMM * DIMM], g_pwl[DIMM * DIMM];
__device__ __nv_bfloat16 g_qkvTh[(size_t)DEPTH * 3 * DIMM * DIMM], g_qkvTl[(size_t)DEPTH * 3 * DIMM * DIMM];
__device__ __nv_bfloat16 g_projTh[(size_t)DEPTH * DIMM * DIMM],    g_projTl[(size_t)DEPTH * DIMM * DIMM];
__device__ __nv_bfloat16 g_w1Th[(size_t)DEPTH * HID * DIMM],       g_w1Tl[(size_t)DEPTH * HID * DIMM];
__device__ __nv_bfloat16 g_w2Th[(size_t)DEPTH * DIMM * HID],       g_w2Tl[(size_t)DEPTH * DIMM * HID];

__device__ __forceinline__ void split_val(float v, __nv_bfloat16& hi, __nv_bfloat16& lo) {
    hi = __float2bfloat16(v);
    lo = __float2bfloat16(v - __bfloat162float(hi));
}

// ======================= prep kernels =======================================
__global__ void patch_extract(const float* __restrict__ x,
                              __nv_bfloat16* __restrict__ ph, __nv_bfloat16* __restrict__ pl) {
    int t = blockIdx.x * blockDim.x + threadIdx.x;
    if (t >= BATCH * NPATCH * DIMM) return;
    int f  = t % DIMM;
    int pr = t / DIMM;
    int b  = pr / NPATCH;
    int i  = pr % NPATCH;
    int gy = i / 24, gx = i % 24;
    int c  = f >> 8;
    int py = (f >> 4) & 15;
    int px = f & 15;
    float v = x[((size_t)(b * 3 + c) * 384 + (gy * 16 + py)) * 384 + (gx * 16 + px)];
    split_val(v, ph[t], pl[t]);
}

__global__ void split_planes(const float* __restrict__ x, __nv_bfloat16* __restrict__ hi,
                             __nv_bfloat16* __restrict__ lo, int n) {
    int t = blockIdx.x * blockDim.x + threadIdx.x;
    if (t < n) split_val(x[t], hi[t], lo[t]);
}

// W [K,N] (per layer, z = layer) -> Wt hi/lo [N,K]
__global__ void tr_split(const float* __restrict__ W, __nv_bfloat16* __restrict__ Th,
                         __nv_bfloat16* __restrict__ Tl, int K, int N) {
    __shared__ float t[32][33];
    size_t off = (size_t)blockIdx.z * K * N;
    int k0 = blockIdx.y * 32, n0 = blockIdx.x * 32;
    int tx = threadIdx.x, ty = threadIdx.y;     // 32 x 8
    #pragma unroll
    for (int i = 0; i < 32; i += 8)
        t[ty + i][tx] = W[off + (size_t)(k0 + ty + i) * N + n0 + tx];
    __syncthreads();
    #pragma unroll
    for (int i = 0; i < 32; i += 8) {
        float v = t[tx][ty + i];                // = W[k0+tx][n0+ty+i]
        size_t o = off + (size_t)(n0 + ty + i) * K + k0 + tx;
        split_val(v, Th[o], Tl[o]);
    }
}

__global__ void add_pos_cls(const float* __restrict__ hp, const float* __restrict__ cls,
                            const float* __restrict__ pos, float* __restrict__ h) {
    int t = blockIdx.x;
    int b = t / NTOK, n = t - b * NTOK;
    for (int d = threadIdx.x; d < DIMM; d += blockDim.x) {
        float v = (n == 0) ? cls[d] : hp[(size_t)(b * NPATCH + n - 1) * DIMM + d];
        h[(size_t)t * DIMM + d] = v + pos[n * DIMM + d];
    }
}

// ======================= LayerNorm ==========================================
template <int SPLIT>
__global__ void __launch_bounds__(256) ln_kernel(
    const float* __restrict__ x, const float* __restrict__ g,
    const float* __restrict__ b, float* __restrict__ yf,
    __nv_bfloat16* __restrict__ yh, __nv_bfloat16* __restrict__ yl,
    float eps, long rstride)
{
    const float* xr = x + (size_t)blockIdx.x * rstride;
    int tid = threadIdx.x;
    float v0 = xr[tid], v1 = xr[tid + 256], v2 = xr[tid + 512];
    float s  = v0 + v1 + v2;
    float sq = v0 * v0 + v1 * v1 + v2 * v2;
    #pragma unroll
    for (int o = 16; o; o >>= 1) {
        s  += __shfl_xor_sync(0xffffffffu, s,  o);
        sq += __shfl_xor_sync(0xffffffffu, sq, o);
    }
    __shared__ float rs[8], rq[8];
    if ((tid & 31) == 0) { rs[tid >> 5] = s; rq[tid >> 5] = sq; }
    __syncthreads();
    if (tid == 0) {
        float ss = 0.f, qq = 0.f;
        #pragma unroll
        for (int i = 0; i < 8; i++) { ss += rs[i]; qq += rq[i]; }
        rs[0] = ss; rq[0] = qq;
    }
    __syncthreads();
    float mean = rs[0] * (1.f / 768.f);
    float var  = rq[0] * (1.f / 768.f) - mean * mean;
    float inv  = rsqrtf(var + eps);
    size_t base = (size_t)blockIdx.x * DIMM;
    #pragma unroll
    for (int u = 0; u < 3; u++) {
        int d = tid + u * 256;
        float vv = (u == 0 ? v0 : (u == 1 ? v1 : v2));
        float o = (vv - mean) * inv * g[d] + b[d];
        if (SPLIT) split_val(o, yh[base + d], yl[base + d]);
        else       yf[base + d] = o;
    }
}

// ======================= split-bf16 mma.sync GEMM ===========================
// C[M,N] = (Ahi+Alo)[M,K] @ (Bhi+Blo)[N,K]^T (+bias, epilogue)
// EPI: 0 = bias -> Cf ; 1 = bias+GELU -> (Chi,Clo) ; 2 = bias+residual -> Cf
// smem: 2 buffers x 4 planes x [128 rows x 40 bf16 (pitch 80B)] = 81920 B
#define PITCH_B 80
#define PLANE   10240
#define BUFSZ   40960
#define MM_SMEM 81920

template <int EPI>
__global__ void __launch_bounds__(256, 2) mma_gemm(
    const __nv_bfloat16* __restrict__ Ahi, const __nv_bfloat16* __restrict__ Alo,
    const __nv_bfloat16* __restrict__ Bhi, const __nv_bfloat16* __restrict__ Blo,
    const float* __restrict__ bias, const float* __restrict__ R,
    float* __restrict__ Cf, __nv_bfloat16* __restrict__ Chi, __nv_bfloat16* __restrict__ Clo,
    int M, int N, int K)
{
    extern __shared__ __align__(128) char smem[];
    const uint32_t sb = smem_u32(smem);
    const int tid = threadIdx.x, wid = tid >> 5, lane = tid & 31;
    const int m0 = blockIdx.y * 128, n0 = blockIdx.x * 128;
    const int wm = (wid & 3) * 32, wn = (wid >> 2) * 64;

    float acc[2][8][4];
    #pragma unroll
    for (int i = 0; i < 2; i++)
        #pragma unroll
        for (int j = 0; j < 8; j++)
            #pragma unroll
            for (int q = 0; q < 4; q++) acc[i][j][q] = 0.f;

    const int nc = K >> 5;                  // chunks of 32

    auto issue = [&](int c, int buf) {
        const int k0 = c << 5;
        const uint32_t base = sb + buf * BUFSZ;
        #pragma unroll
        for (int i = 0; i < 2; i++) {
            int idx = tid + i * 256;        // 0..511
            int row = idx >> 2, seg = idx & 3;
            uint32_t soff = (uint32_t)(row * PITCH_B + seg * 16);
            int am = m0 + row;
            uint32_t asz = (am < M) ? 16u : 0u;
            size_t ao = (size_t)am * K + k0 + seg * 8;
            cp16(base + soff,             Ahi + ao, asz);
            cp16(base + PLANE + soff,     Alo + ao, asz);
            size_t bo = (size_t)(n0 + row) * K + k0 + seg * 8;
            cp16(base + 2 * PLANE + soff, Bhi + bo, 16u);
            cp16(base + 3 * PLANE + soff, Blo + bo, 16u);
        }
        asm volatile("cp.async.commit_group;" ::: "memory");
    };

    issue(0, 0);

    const int lr = (lane & 7) + (lane & 8);     // row offset in 16-row tile
    const int lc = (lane & 16) ? 8 : 0;         // col offset

    for (int c = 0; c < nc; c++) {
        if (c + 1 < nc) {
            issue(c + 1, (c + 1) & 1);
            asm volatile("cp.async.wait_group 1;" ::: "memory");
        } else {
            asm volatile("cp.async.wait_group 0;" ::: "memory");
        }
        __syncthreads();

        const uint32_t base = sb + (c & 1) * BUFSZ;
        #pragma unroll
        for (int ks = 0; ks < 2; ks++) {
            const int kk = ks * 16;
            uint32_t ah[2][4], al[2][4], bf[4][4];
            #pragma unroll
            for (int mt = 0; mt < 2; mt++)
                ldm_x4(base + (uint32_t)((wm + mt * 16 + lr) * PITCH_B + (kk + lc) * 2), ah[mt]);
            #pragma unroll
            for (int g = 0; g < 4; g++)
                ldm_x4(base + 2 * PLANE + (uint32_t)((wn + g * 16 + lr) * PITCH_B + (kk + lc) * 2), bf[g]);
            // hi * hi
            #pragma unroll
            for (int mt = 0; mt < 2; mt++)
                #pragma unroll
                for (int nt = 0; nt < 8; nt++) {
                    int g = nt >> 1, o = nt & 1;
                    mma16816(acc[mt][nt], ah[mt], bf[g][o], bf[g][o + 2]);
                }
            // lo * hi
            #pragma unroll
            for (int mt = 0; mt < 2; mt++)
                ldm_x4(base + PLANE + (uint32_t)((wm + mt * 16 + lr) * PITCH_B + (kk + lc) * 2), al[mt]);
            #pragma unroll
            for (int mt = 0; mt < 2; mt++)
                #pragma unroll
                for (int nt = 0; nt < 8; nt++) {
                    int g = nt >> 1, o = nt & 1;
                    mma16816(acc[mt][nt], al[mt], bf[g][o], bf[g][o + 2]);
                }
            // hi * lo
            #pragma unroll
            for (int g = 0; g < 4; g++)
                ldm_x4(base + 3 * PLANE + (uint32_t)((wn + g * 16 + lr) * PITCH_B + (kk + lc) * 2), bf[g]);
            #pragma unroll
            for (int mt = 0; mt < 2; mt++)
                #pragma unroll
                for (int nt = 0; nt < 8; nt++) {
                    int g = nt >> 1, o = nt & 1;
                    mma16816(acc[mt][nt], ah[mt], bf[g][o], bf[g][o + 2]);
                }
        }
        __syncthreads();
    }

    // epilogue: thread holds (m = lane/4 + 8h, n = (lane%4)*2 + {0,1}) per tile
    #pragma unroll
    for (int mt = 0; mt < 2; mt++) {
        #pragma unroll
        for (int h2 = 0; h2 < 2; h2++) {
            int m = m0 + wm + mt * 16 + (lane >> 2) + h2 * 8;
            if (m >= M) continue;
            #pragma unroll
            for (int nt = 0; nt < 8; nt++) {
                int n = n0 + wn + nt * 8 + (lane & 3) * 2;
                float v0 = acc[mt][nt][h2 * 2]     + bias[n];
                float v1 = acc[mt][nt][h2 * 2 + 1] + bias[n + 1];
                size_t o = (size_t)m * N + n;
                if (EPI == 1) {
                    v0 = 0.5f * v0 * (1.f + erff(v0 * 0.70710678118654752f));
                    v1 = 0.5f * v1 * (1.f + erff(v1 * 0.70710678118654752f));
                    __nv_bfloat16 h0, l0, h1, l1;
                    split_val(v0, h0, l0);
                    split_val(v1, h1, l1);
                    __nv_bfloat162 hh; hh.x = h0; hh.y = h1;
                    __nv_bfloat162 ll; ll.x = l0; ll.y = l1;
                    *(__nv_bfloat162*)(Chi + o) = hh;
                    *(__nv_bfloat162*)(Clo + o) = ll;
                } else {
                    if (EPI == 2) {
                        float2 rr = *(const float2*)(R + o);
                        v0 += rr.x; v1 += rr.y;
                    }
                    float2 vv; vv.x = v0; vv.y = v1;
                    *(float2*)(Cf + o) = vv;
                }
            }
        }
    }
}

// ======================= fp32 GEMM (head only) ==============================
__global__ void __launch_bounds__(256) gemm_f32(
    const float* __restrict__ A, const float* __restrict__ Bm,
    const float* __restrict__ bias, float* __restrict__ C, int M, int N, int K)
{
    __shared__ float As[16][132];
    __shared__ float Bs[16][132];
    int tid = threadIdx.x;
    int m0 = blockIdx.y * 128, n0 = blockIdx.x * 128;
    int ty = tid >> 4, tx = tid & 15;
    float acc[8][8] = {};
    for (int k0 = 0; k0 < K; k0 += 16) {
        #pragma unroll
        for (int s = 0; s < 2; s++) {
            int idx = tid + s * 256;
            int r = idx >> 2, kq = idx & 3;
            float4 v = make_float4(0.f, 0.f, 0.f, 0.f);
            if (m0 + r < M)
                v = *(const float4*)(A + (size_t)(m0 + r) * K + k0 + kq * 4);
            As[kq * 4 + 0][r] = v.x; As[kq * 4 + 1][r] = v.y;
            As[kq * 4 + 2][r] = v.z; As[kq * 4 + 3][r] = v.w;
        }
        #pragma unroll
        for (int s = 0; s < 2; s++) {
            int idx = tid + s * 256;
            int r = idx >> 5, nq = idx & 31;
            float4 v = make_float4(0.f, 0.f, 0.f, 0.f);
            if (n0 + nq * 4 < N)
                v = *(const float4*)(Bm + (size_t)(k0 + r) * N + n0 + nq * 4);
            *(float4*)&Bs[r][nq * 4] = v;
        }
        __syncthreads();
        #pragma unroll
        for (int kk = 0; kk < 16; kk++) {
            float4 a0 = *(float4*)&As[kk][ty * 8];
            float4 a1 = *(float4*)&As[kk][ty * 8 + 4];
            float4 b0 = *(float4*)&Bs[kk][tx * 8];
            float4 b1 = *(float4*)&Bs[kk][tx * 8 + 4];
            float ar[8] = {a0.x, a0.y, a0.z, a0.w, a1.x, a1.y, a1.z, a1.w};
            float br[8] = {b0.x, b0.y, b0.z, b0.w, b1.x, b1.y, b1.z, b1.w};
            #pragma unroll
            for (int i = 0; i < 8; i++)
                #pragma unroll
                for (int j = 0; j < 8; j++)
                    acc[i][j] = fmaf(ar[i], br[j], acc[i][j]);
        }
        __syncthreads();
    }
    #pragma unroll
    for (int i = 0; i < 8; i++) {
        int m = m0 + ty * 8 + i;
        if (m >= M) continue;
        #pragma unroll
        for (int j = 0; j < 8; j++) {
            int n = n0 + tx * 8 + j;
            if (n < N) C[(size_t)m * N + n] = acc[i][j] + bias[n];
        }
    }
}

// ======================= attention (fp32) ===================================
__global__ void __launch_bounds__(256) attn_scores(
    const float* __restrict__ qkv, float* __restrict__ S)
{
    int bh = blockIdx.z;
    int b = bh / NHEAD, h = bh - b * NHEAD;
    int q0 = blockIdx.x * 64, k0 = blockIdx.y * 64;
    __shared__ float Qs[64][68], Ks[64][68];
    int tid = threadIdx.x;
    #pragma unroll
    for (int s = 0; s < 4; s++) {
        int idx = tid + s * 256;
        int r = idx >> 4, c4 = idx & 15;
        int q = q0 + r;
        float4 v = make_float4(0.f, 0.f, 0.f, 0.f);
        if (q < NTOK)
            v = *(const float4*)(qkv + (size_t)(b * NTOK + q) * (3 * DIMM) + h * HD + c4 * 4);
        *(float4*)&Qs[r][c4 * 4] = v;
        int k = k0 + r;
        float4 w = make_float4(0.f, 0.f, 0.f, 0.f);
        if (k < NTOK)
            w = *(const float4*)(qkv + (size_t)(b * NTOK + k) * (3 * DIMM) + DIMM + h * HD + c4 * 4);
        *(float4*)&Ks[r][c4 * 4] = w;
    }
    __syncthreads();
    int ty = tid >> 4, tx = tid & 15;
    float acc[4][4] = {};
    #pragma unroll 8
    for (int d = 0; d < HD; d++) {
        float a[4], bb[4];
        #pragma unroll
        for (int i = 0; i < 4; i++) a[i]  = Qs[ty * 4 + i][d];
        #pragma unroll
        for (int j = 0; j < 4; j++) bb[j] = Ks[tx * 4 + j][d];
        #pragma unroll
        for (int i = 0; i < 4; i++)
            #pragma unroll
            for (int j = 0; j < 4; j++)
                acc[i][j] = fmaf(a[i], bb[j], acc[i][j]);
    }
    #pragma unroll
    for (int i = 0; i < 4; i++) {
        int q = q0 + ty * 4 + i;
        if (q >= NTOK) continue;
        #pragma unroll
        for (int j = 0; j < 4; j++) {
            int k = k0 + tx * 4 + j;
            if (k < NTOK)
                S[((size_t)bh * NTOK + q) * NTOK + k] = acc[i][j] * 0.125f;
        }
    }
}

__global__ void __launch_bounds__(256) softmax_rows(float* __restrict__ S) {
    float* p = S + (size_t)blockIdx.x * NTOK;
    int tid = threadIdx.x;
    bool ok1 = (tid + 256) < NTOK, ok2 = (tid + 512) < NTOK;
    float v0 = p[tid];
    float v1 = ok1 ? p[tid + 256] : -1e30f;
    float v2 = ok2 ? p[tid + 512] : -1e30f;
    float m = fmaxf(fmaxf(v0, v1), v2);
    #pragma unroll
    for (int o = 16; o; o >>= 1) m = fmaxf(m, __shfl_xor_sync(0xffffffffu, m, o));
    __shared__ float red[8];
    if ((tid & 31) == 0) red[tid >> 5] = m;
    __syncthreads();
    if (tid == 0) {
        float mm = red[0];
        #pragma unroll
        for (int i = 1; i < 8; i++) mm = fmaxf(mm, red[i]);
        red[0] = mm;
    }
    __syncthreads();
    m = red[0];
    __syncthreads();
    float e0 = __expf(v0 - m);
    float e1 = ok1 ? __expf(v1 - m) : 0.f;
    float e2 = ok2 ? __expf(v2 - m) : 0.f;
    float s = e0 + e1 + e2;
    #pragma unroll
    for (int o = 16; o; o >>= 1) s += __shfl_xor_sync(0xffffffffu, s, o);
    if ((tid & 31) == 0) red[tid >> 5] = s;
    __syncthreads();
    if (tid == 0) {
        float ss = 0.f;
        #pragma unroll
        for (int i = 0; i < 8; i++) ss += red[i];
        red[0] = ss;
    }
    __syncthreads();
    float inv = 1.f / red[0];
    p[tid] = e0 * inv;
    if (ok1) p[tid + 256] = e1 * inv;
    if (ok2) p[tid + 512] = e2 * inv;
}

__global__ void __launch_bounds__(256) attn_av(
    const float* __restrict__ S, const float* __restrict__ qkv,
    __nv_bfloat16* __restrict__ Oh, __nv_bfloat16* __restrict__ Ol)
{
    int bh = blockIdx.y;
    int b = bh / NHEAD, h = bh - b * NHEAD;
    int q0 = blockIdx.x * 64;
    __shared__ float Ps[64][65];
    __shared__ float Vs[64][68];
    int tid = threadIdx.x, ty = tid >> 4, tx = tid & 15;
    float acc[4][4] = {};
    for (int k0 = 0; k0 < NTOK; k0 += 64) {
        #pragma unroll
        for (int s = 0; s < 16; s++) {
            int idx = tid + s * 256;
            int r = idx >> 6, c = idx & 63;
            float v = 0.f;
            if (q0 + r < NTOK && k0 + c < NTOK)
                v = S[((size_t)bh * NTOK + q0 + r) * NTOK + k0 + c];
            Ps[r][c] = v;
        }
        #pragma unroll
        for (int s = 0; s < 4; s++) {
            int idx = tid + s * 256;
            int r = idx >> 4, c4 = idx & 15;
            float4 v = make_float4(0.f, 0.f, 0.f, 0.f);
            if (k0 + r < NTOK)
                v = *(const float4*)(qkv + (size_t)(b * NTOK + k0 + r) * (3 * DIMM) + 2 * DIMM + h * HD + c4 * 4);
            *(float4*)&Vs[r][c4 * 4] = v;
        }
        __syncthreads();
        #pragma unroll 4
        for (int kk = 0; kk < 64; kk++) {
            float4 vv = *(float4*)&Vs[kk][tx * 4];
            float pr[4];
            #pragma unroll
            for (int i = 0; i < 4; i++) pr[i] = Ps[ty * 4 + i][kk];
            #pragma unroll
            for (int i = 0; i < 4; i++) {
                acc[i][0] = fmaf(pr[i], vv.x, acc[i][0]);
                acc[i][1] = fmaf(pr[i], vv.y, acc[i][1]);
                acc[i][2] = fmaf(pr[i], vv.z, acc[i][2]);
                acc[i][3] = fmaf(pr[i], vv.w, acc[i][3]);
            }
        }
        __syncthreads();
    }
    #pragma unroll
    for (int i = 0; i < 4; i++) {
        int q = q0 + ty * 4 + i;
        if (q >= NTOK) continue;
        size_t base = (size_t)(b * NTOK + q) * DIMM + h * HD + tx * 4;
        #pragma unroll
        for (int j = 0; j < 4; j++)
            split_val(acc[i][j], Oh[base + j], Ol[base + j]);
    }
}

// ======================= host driver ========================================
extern "C" void kernel_launch(void* const* d_in, const int* in_sizes, int n_in,
                              void* d_out, int out_size)
{
    const float* x       = (const float*)d_in[0];
    const float* patch_w = (const float*)d_in[1];
    const float* patch_b = (const float*)d_in[2];
    const float* cls_t   = (const float*)d_in[3];
    const float* pos     = (const float*)d_in[4];
    const float* ln1_g   = (const float*)d_in[5];
    const float* ln1_b   = (const float*)d_in[6];
    const float* qkv_w   = (const float*)d_in[7];
    const float* qkv_b   = (const float*)d_in[8];
    const float* proj_w  = (const float*)d_in[9];
    const float* proj_b  = (const float*)d_in[10];
    const float* ln2_g   = (const float*)d_in[11];
    const float* ln2_b   = (const float*)d_in[12];
    const float* w1      = (const float*)d_in[13];
    const float* b1      = (const float*)d_in[14];
    const float* w2      = (const float*)d_in[15];
    const float* b2      = (const float*)d_in[16];
    const float* lnf_g   = (const float*)d_in[17];
    const float* lnf_b   = (const float*)d_in[18];
    const float* head_w  = (const float*)d_in[19];
    const float* head_b  = (const float*)d_in[20];
    float* out = (float*)d_out;

    cudaFuncSetAttribute(mma_gemm<0>, cudaFuncAttributeMaxDynamicSharedMemorySize, MM_SMEM);
    cudaFuncSetAttribute(mma_gemm<1>, cudaFuncAttributeMaxDynamicSharedMemorySize, MM_SMEM);
    cudaFuncSetAttribute(mma_gemm<2>, cudaFuncAttributeMaxDynamicSharedMemorySize, MM_SMEM);

    float *h, *qkv, *S, *hp, *cls;
    cudaGetSymbolAddress((void**)&h,   g_h);
    cudaGetSymbolAddress((void**)&qkv, g_qkv);
    cudaGetSymbolAddress((void**)&S,   g_S);
    cudaGetSymbolAddress((void**)&hp,  g_hp);
    cudaGetSymbolAddress((void**)&cls, g_cls);
    __nv_bfloat16 *yh, *yl, *ath, *atl, *mh, *ml, *pph, *ppl, *pwh, *pwl;
    __nv_bfloat16 *qTh, *qTl, *pTh, *pTl, *w1h, *w1l, *w2h, *w2l;
    cudaGetSymbolAddress((void**)&yh,  g_yh);   cudaGetSymbolAddress((void**)&yl,  g_yl);
    cudaGetSymbolAddress((void**)&ath, g_ath);  cudaGetSymbolAddress((void**)&atl, g_atl);
    cudaGetSymbolAddress((void**)&mh,  g_mh);   cudaGetSymbolAddress((void**)&ml,  g_ml);
    cudaGetSymbolAddress((void**)&pph, g_ph);   cudaGetSymbolAddress((void**)&ppl, g_pl);
    cudaGetSymbolAddress((void**)&pwh, g_pwh);  cudaGetSymbolAddress((void**)&pwl, g_pwl);
    cudaGetSymbolAddress((void**)&qTh, g_qkvTh);  cudaGetSymbolAddress((void**)&qTl, g_qkvTl);
    cudaGetSymbolAddress((void**)&pTh, g_projTh); cudaGetSymbolAddress((void**)&pTl, g_projTl);
    cudaGetSymbolAddress((void**)&w1h, g_w1Th);   cudaGetSymbolAddress((void**)&w1l, g_w1Tl);
    cudaGetSymbolAddress((void**)&w2h, g_w2Th);   cudaGetSymbolAddress((void**)&w2l, g_w2Tl);

    dim3 t328(32, 8);
    // weight prep
    split_planes<<<(DIMM * DIMM + 255) / 256, 256>>>(patch_w, pwh, pwl, DIMM * DIMM);
    tr_split<<<dim3(72, 24, DEPTH), t328>>>(qkv_w,  qTh, qTl, DIMM, 3 * DIMM);
    tr_split<<<dim3(24, 24, DEPTH), t328>>>(proj_w, pTh, pTl, DIMM, DIMM);
    tr_split<<<dim3(96, 24, DEPTH), t328>>>(w1,     w1h, w1l, DIMM, HID);
    tr_split<<<dim3(24, 96, DEPTH), t328>>>(w2,     w2h, w2l, HID, DIMM);

    // patch embed
    patch_extract<<<(BATCH * NPATCH * DIMM + 255) / 256, 256>>>(x, pph, ppl);
    mma_gemm<0><<<dim3(6, 36), 256, MM_SMEM>>>(pph, ppl, pwh, pwl, patch_b, nullptr,
                                               hp, nullptr, nullptr,
                                               BATCH * NPATCH, DIMM, DIMM);
    add_pos_cls<<<TOKS, 256>>>(hp, cls_t, pos, h);

    for (int l = 0; l < DEPTH; l++) {
        ln_kernel<1><<<TOKS, 256>>>(h, ln1_g + l * DIMM, ln1_b + l * DIMM,
                                    nullptr, yh, yl, 1e-5f, DIMM);
        mma_gemm<0><<<dim3(18, 37), 256, MM_SMEM>>>(
            yh, yl, qTh + (size_t)l * 3 * DIMM * DIMM, qTl + (size_t)l * 3 * DIMM * DIMM,
            qkv_b + l * 3 * DIMM, nullptr, qkv, nullptr, nullptr, TOKS, 3 * DIMM, DIMM);
        attn_scores<<<dim3(10, 10, BATCH * NHEAD), 256>>>(qkv, S);
        softmax_rows<<<BATCH * NHEAD * NTOK, 256>>>(S);
        attn_av<<<dim3(10, BATCH * NHEAD), 256>>>(S, qkv, ath, atl);
        mma_gemm<2><<<dim3(6, 37), 256, MM_SMEM>>>(
            ath, atl, pTh + (size_t)l * DIMM * DIMM, pTl + (size_t)l * DIMM * DIMM,
            proj_b + l * DIMM, h, h, nullptr, nullptr, TOKS, DIMM, DIMM);
        ln_kernel<1><<<TOKS, 256>>>(h, ln2_g + l * DIMM, ln2_b + l * DIMM,
                                    nullptr, yh, yl, 1e-5f, DIMM);
        mma_gemm<1><<<dim3(24, 37), 256, MM_SMEM>>>(
            yh, yl, w1h + (size_t)l * HID * DIMM, w1l + (size_t)l * HID * DIMM,
            b1 + l * HID, nullptr, nullptr, mh, ml, TOKS, HID, DIMM);
        mma_gemm<2><<<dim3(6, 37), 256, MM_SMEM>>>(
            mh, ml, w2h + (size_t)l * DIMM * HID, w2l + (size_t)l * DIMM * HID,
            b2 + l * DIMM, h, h, nullptr, nullptr, TOKS, DIMM, HID);
    }

    ln_kernel<0><<<BATCH, 256>>>(h, lnf_g, lnf_b, cls, nullptr, nullptr,
                                 1e-6f, (long)NTOK * DIMM);
    gemm_f32<<<dim3(8, 1), 256>>>(cls, head_w, head_b, out, BATCH, 1000, DIMM);
}

// round 6
// speedup vs baseline: 2.4876x; 1.4120x over previous
#include <cuda_runtime.h>
#include <cuda_bf16.h>
#include <cstdint>
#include <cstddef>

#define NTOK   577
#define DIMM   768
#define NHEAD  12
#define HD     64
#define HID    3072
#define BATCH  8
#define TOKS   (BATCH * NTOK)      // 4616
#define NPATCH 576
#define DEPTH  12
#define BH     (BATCH * NHEAD)     // 96
#define PQ     640                 // padded token dim for attention (10 x 64)

// ======================= asm helpers (sm_80+ only) ==========================
__device__ __forceinline__ uint32_t smem_u32(const void* p) {
    uint32_t a;
    asm("{ .reg .u64 t; cvta.to.shared.u64 t, %1; cvt.u32.u64 %0, t; }" : "=r"(a) : "l"(p));
    return a;
}
__device__ __forceinline__ void cp16(uint32_t s, const void* g, uint32_t sz) {
    asm volatile("cp.async.cg.shared.global [%0], [%1], 16, %2;"
                 :: "r"(s), "l"(g), "r"(sz));
}
__device__ __forceinline__ void ldm_x4(uint32_t addr, uint32_t* r) {
    asm volatile("ldmatrix.sync.aligned.m8n8.x4.shared.b16 {%0,%1,%2,%3}, [%4];"
                 : "=r"(r[0]), "=r"(r[1]), "=r"(r[2]), "=r"(r[3]) : "r"(addr));
}
__device__ __forceinline__ void ldm_x4_t(uint32_t addr, uint32_t* r) {
    asm volatile("ldmatrix.sync.aligned.m8n8.x4.trans.shared.b16 {%0,%1,%2,%3}, [%4];"
                 : "=r"(r[0]), "=r"(r[1]), "=r"(r[2]), "=r"(r[3]) : "r"(addr));
}
__device__ __forceinline__ void mma16816(float* c, const uint32_t* a, uint32_t b0, uint32_t b1) {
    asm volatile(
        "mma.sync.aligned.m16n8k16.row.col.f32.bf16.bf16.f32 "
        "{%0,%1,%2,%3}, {%4,%5,%6,%7}, {%8,%9}, {%0,%1,%2,%3};"
        : "+f"(c[0]), "+f"(c[1]), "+f"(c[2]), "+f"(c[3])
        : "r"(a[0]), "r"(a[1]), "r"(a[2]), "r"(a[3]), "r"(b0), "r"(b1));
}

// ======================= scratch ============================================
__device__ float g_h[TOKS * DIMM];
__device__ float g_hp[BATCH * NPATCH * DIMM];
__device__ float g_cls[BATCH * DIMM];
__device__ float g_l[BH * PQ];

__device__ __nv_bfloat16 g_yh[TOKS * DIMM],  g_yl[TOKS * DIMM];
__device__ __nv_bfloat16 g_qkvh[(size_t)TOKS * 3 * DIMM], g_qkvl[(size_t)TOKS * 3 * DIMM];
__device__ __nv_bfloat16 g_Ph[(size_t)BH * PQ * PQ], g_Pl[(size_t)BH * PQ * PQ];
__device__ __nv_bfloat16 g_ath[TOKS * DIMM], g_atl[TOKS * DIMM];
__device__ __nv_bfloat16 g_mh[(size_t)TOKS * HID], g_ml[(size_t)TOKS * HID];
__device__ __nv_bfloat16 g_ph[BATCH * NPATCH * DIMM], g_pl[BATCH * NPATCH * DIMM];
__device__ __nv_bfloat16 g_pwh[DIMM * DIMM], g_pwl[DIMM * DIMM];
__device__ __nv_bfloat16 g_qkvTh[(size_t)DEPTH * 3 * DIMM * DIMM], g_qkvTl[(size_t)DEPTH * 3 * DIMM * DIMM];
__device__ __nv_bfloat16 g_projTh[(size_t)DEPTH * DIMM * DIMM],    g_projTl[(size_t)DEPTH * DIMM * DIMM];
__device__ __nv_bfloat16 g_w1Th[(size_t)DEPTH * HID * DIMM],       g_w1Tl[(size_t)DEPTH * HID * DIMM];
__device__ __nv_bfloat16 g_w2Th[(size_t)DEPTH * DIMM * HID],       g_w2Tl[(size_t)DEPTH * DIMM * HID];

__device__ __forceinline__ void split_val(float v, __nv_bfloat16& hi, __nv_bfloat16& lo) {
    hi = __float2bfloat16(v);
    lo = __float2bfloat16(v - __bfloat162float(hi));
}

// ======================= prep kernels =======================================
__global__ void patch_extract(const float* __restrict__ x,
                              __nv_bfloat16* __restrict__ ph, __nv_bfloat16* __restrict__ pl) {
    int t = blockIdx.x * blockDim.x + threadIdx.x;
    if (t >= BATCH * NPATCH * DIMM) return;
    int f  = t % DIMM;
    int pr = t / DIMM;
    int b  = pr / NPATCH;
    int i  = pr % NPATCH;
    int gy = i / 24, gx = i % 24;
    int c  = f >> 8;
    int py = (f >> 4) & 15;
    int px = f & 15;
    float v = x[((size_t)(b * 3 + c) * 384 + (gy * 16 + py)) * 384 + (gx * 16 + px)];
    split_val(v, ph[t], pl[t]);
}

__global__ void split_planes(const float* __restrict__ x, __nv_bfloat16* __restrict__ hi,
                             __nv_bfloat16* __restrict__ lo, int n) {
    int t = blockIdx.x * blockDim.x + threadIdx.x;
    if (t < n) split_val(x[t], hi[t], lo[t]);
}

__global__ void tr_split(const float* __restrict__ W, __nv_bfloat16* __restrict__ Th,
                         __nv_bfloat16* __restrict__ Tl, int K, int N) {
    __shared__ float t[32][33];
    size_t off = (size_t)blockIdx.z * K * N;
    int k0 = blockIdx.y * 32, n0 = blockIdx.x * 32;
    int tx = threadIdx.x, ty = threadIdx.y;     // 32 x 8
    #pragma unroll
    for (int i = 0; i < 32; i += 8)
        t[ty + i][tx] = W[off + (size_t)(k0 + ty + i) * N + n0 + tx];
    __syncthreads();
    #pragma unroll
    for (int i = 0; i < 32; i += 8) {
        float v = t[tx][ty + i];
        size_t o = off + (size_t)(n0 + ty + i) * K + k0 + tx;
        split_val(v, Th[o], Tl[o]);
    }
}

__global__ void add_pos_cls(const float* __restrict__ hp, const float* __restrict__ cls,
                            const float* __restrict__ pos, float* __restrict__ h) {
    int t = blockIdx.x;
    int b = t / NTOK, n = t - b * NTOK;
    for (int d = threadIdx.x; d < DIMM; d += blockDim.x) {
        float v = (n == 0) ? cls[d] : hp[(size_t)(b * NPATCH + n - 1) * DIMM + d];
        h[(size_t)t * DIMM + d] = v + pos[n * DIMM + d];
    }
}

// ======================= LayerNorm ==========================================
template <int SPLIT>
__global__ void __launch_bounds__(256) ln_kernel(
    const float* __restrict__ x, const float* __restrict__ g,
    const float* __restrict__ b, float* __restrict__ yf,
    __nv_bfloat16* __restrict__ yh, __nv_bfloat16* __restrict__ yl,
    float eps, long rstride)
{
    const float* xr = x + (size_t)blockIdx.x * rstride;
    int tid = threadIdx.x;
    float v0 = xr[tid], v1 = xr[tid + 256], v2 = xr[tid + 512];
    float s  = v0 + v1 + v2;
    float sq = v0 * v0 + v1 * v1 + v2 * v2;
    #pragma unroll
    for (int o = 16; o; o >>= 1) {
        s  += __shfl_xor_sync(0xffffffffu, s,  o);
        sq += __shfl_xor_sync(0xffffffffu, sq, o);
    }
    __shared__ float rs[8], rq[8];
    if ((tid & 31) == 0) { rs[tid >> 5] = s; rq[tid >> 5] = sq; }
    __syncthreads();
    if (tid == 0) {
        float ss = 0.f, qq = 0.f;
        #pragma unroll
        for (int i = 0; i < 8; i++) { ss += rs[i]; qq += rq[i]; }
        rs[0] = ss; rq[0] = qq;
    }
    __syncthreads();
    float mean = rs[0] * (1.f / 768.f);
    float var  = rq[0] * (1.f / 768.f) - mean * mean;
    float inv  = rsqrtf(var + eps);
    size_t base = (size_t)blockIdx.x * DIMM;
    #pragma unroll
    for (int u = 0; u < 3; u++) {
        int d = tid + u * 256;
        float vv = (u == 0 ? v0 : (u == 1 ? v1 : v2));
        float o = (vv - mean) * inv * g[d] + b[d];
        if (SPLIT) split_val(o, yh[base + d], yl[base + d]);
        else       yf[base + d] = o;
    }
}

// ======================= split-bf16 mma.sync GEMM ===========================
// EPI: 0 = bias -> Cf ; 1 = bias+GELU -> (Chi,Clo) ; 2 = bias+res -> Cf ;
//      3 = bias -> (Chi,Clo)
#define PITCH_B 80
#define PLANE   10240
#define BUFSZ   40960
#define MM_SMEM 81920

template <int EPI>
__global__ void __launch_bounds__(256, 2) mma_gemm(
    const __nv_bfloat16* __restrict__ Ahi, const __nv_bfloat16* __restrict__ Alo,
    const __nv_bfloat16* __restrict__ Bhi, const __nv_bfloat16* __restrict__ Blo,
    const float* __restrict__ bias, const float* __restrict__ R,
    float* __restrict__ Cf, __nv_bfloat16* __restrict__ Chi, __nv_bfloat16* __restrict__ Clo,
    int M, int N, int K)
{
    extern __shared__ __align__(128) char smem[];
    const uint32_t sb = smem_u32(smem);
    const int tid = threadIdx.x, wid = tid >> 5, lane = tid & 31;
    const int m0 = blockIdx.y * 128, n0 = blockIdx.x * 128;
    const int wm = (wid & 3) * 32, wn = (wid >> 2) * 64;

    float acc[2][8][4];
    #pragma unroll
    for (int i = 0; i < 2; i++)
        #pragma unroll
        for (int j = 0; j < 8; j++)
            #pragma unroll
            for (int q = 0; q < 4; q++) acc[i][j][q] = 0.f;

    const int nc = K >> 5;

    auto issue = [&](int c, int buf) {
        const int k0 = c << 5;
        const uint32_t base = sb + buf * BUFSZ;
        #pragma unroll
        for (int i = 0; i < 2; i++) {
            int idx = tid + i * 256;
            int row = idx >> 2, seg = idx & 3;
            uint32_t soff = (uint32_t)(row * PITCH_B + seg * 16);
            int am = m0 + row;
            uint32_t asz = (am < M) ? 16u : 0u;
            size_t ao = (size_t)am * K + k0 + seg * 8;
            cp16(base + soff,             Ahi + ao, asz);
            cp16(base + PLANE + soff,     Alo + ao, asz);
            size_t bo = (size_t)(n0 + row) * K + k0 + seg * 8;
            cp16(base + 2 * PLANE + soff, Bhi + bo, 16u);
            cp16(base + 3 * PLANE + soff, Blo + bo, 16u);
        }
        asm volatile("cp.async.commit_group;" ::: "memory");
    };

    issue(0, 0);

    const int lr = (lane & 7) + (lane & 8);
    const int lc = (lane & 16) ? 8 : 0;

    for (int c = 0; c < nc; c++) {
        if (c + 1 < nc) {
            issue(c + 1, (c + 1) & 1);
            asm volatile("cp.async.wait_group 1;" ::: "memory");
        } else {
            asm volatile("cp.async.wait_group 0;" ::: "memory");
        }
        __syncthreads();

        const uint32_t base = sb + (c & 1) * BUFSZ;
        #pragma unroll
        for (int ks = 0; ks < 2; ks++) {
            const int kk = ks * 16;
            uint32_t ah[2][4], al[2][4], bf[4][4];
            #pragma unroll
            for (int mt = 0; mt < 2; mt++)
                ldm_x4(base + (uint32_t)((wm + mt * 16 + lr) * PITCH_B + (kk + lc) * 2), ah[mt]);
            #pragma unroll
            for (int g = 0; g < 4; g++)
                ldm_x4(base + 2 * PLANE + (uint32_t)((wn + g * 16 + lr) * PITCH_B + (kk + lc) * 2), bf[g]);
            #pragma unroll
            for (int mt = 0; mt < 2; mt++)
                #pragma unroll
                for (int nt = 0; nt < 8; nt++) {
                    int g = nt >> 1, o = nt & 1;
                    mma16816(acc[mt][nt], ah[mt], bf[g][o], bf[g][o + 2]);
                }
            #pragma unroll
            for (int mt = 0; mt < 2; mt++)
                ldm_x4(base + PLANE + (uint32_t)((wm + mt * 16 + lr) * PITCH_B + (kk + lc) * 2), al[mt]);
            #pragma unroll
            for (int mt = 0; mt < 2; mt++)
                #pragma unroll
                for (int nt = 0; nt < 8; nt++) {
                    int g = nt >> 1, o = nt & 1;
                    mma16816(acc[mt][nt], al[mt], bf[g][o], bf[g][o + 2]);
                }
            #pragma unroll
            for (int g = 0; g < 4; g++)
                ldm_x4(base + 3 * PLANE + (uint32_t)((wn + g * 16 + lr) * PITCH_B + (kk + lc) * 2), bf[g]);
            #pragma unroll
            for (int mt = 0; mt < 2; mt++)
                #pragma unroll
                for (int nt = 0; nt < 8; nt++) {
                    int g = nt >> 1, o = nt & 1;
                    mma16816(acc[mt][nt], ah[mt], bf[g][o], bf[g][o + 2]);
                }
        }
        __syncthreads();
    }

    #pragma unroll
    for (int mt = 0; mt < 2; mt++) {
        #pragma unroll
        for (int h2 = 0; h2 < 2; h2++) {
            int m = m0 + wm + mt * 16 + (lane >> 2) + h2 * 8;
            if (m >= M) continue;
            #pragma unroll
            for (int nt = 0; nt < 8; nt++) {
                int n = n0 + wn + nt * 8 + (lane & 3) * 2;
                float v0 = acc[mt][nt][h2 * 2]     + bias[n];
                float v1 = acc[mt][nt][h2 * 2 + 1] + bias[n + 1];
                size_t o = (size_t)m * N + n;
                if (EPI == 1 || EPI == 3) {
                    if (EPI == 1) {
                        v0 = 0.5f * v0 * (1.f + erff(v0 * 0.70710678118654752f));
                        v1 = 0.5f * v1 * (1.f + erff(v1 * 0.70710678118654752f));
                    }
                    __nv_bfloat16 h0, l0, h1, l1;
                    split_val(v0, h0, l0);
                    split_val(v1, h1, l1);
                    __nv_bfloat162 hh; hh.x = h0; hh.y = h1;
                    __nv_bfloat162 ll; ll.x = l0; ll.y = l1;
                    *(__nv_bfloat162*)(Chi + o) = hh;
                    *(__nv_bfloat162*)(Clo + o) = ll;
                } else {
                    if (EPI == 2) {
                        float2 rr = *(const float2*)(R + o);
                        v0 += rr.x; v1 += rr.y;
                    }
                    float2 vv; vv.x = v0; vv.y = v1;
                    *(float2*)(Cf + o) = vv;
                }
            }
        }
    }
}

// ======================= attention: P = exp(QK^T/8), row sums ===============
// grid (5 q-tiles of 128, 96 bh), block 256 (8 warps, m16 each)
#define AP 144               // 72 bf16 pitch in bytes
#define SC_SMEM 73728

__global__ void __launch_bounds__(256) attn_pexp(
    const __nv_bfloat16* __restrict__ qvh, const __nv_bfloat16* __restrict__ qvl,
    __nv_bfloat16* __restrict__ Ph, __nv_bfloat16* __restrict__ Pl,
    float* __restrict__ lsum)
{
    extern __shared__ __align__(128) char smem[];
    const uint32_t sb = smem_u32(smem);
    const int tid = threadIdx.x, wid = tid >> 5, lane = tid & 31;
    const int qt = blockIdx.x, bh = blockIdx.y;
    const int b = bh / NHEAD, h = bh - b * NHEAD;
    const int q0 = qt * 128;
    const uint32_t QH = sb, QL = sb + 18432, KST = sb + 36864;

    // Q tile (once) — part of cp.async group 0
    #pragma unroll
    for (int i = 0; i < 4; i++) {
        int idx = tid + i * 256;
        int r = idx >> 3, sg = idx & 7;
        int tok = q0 + r;
        uint32_t sz = (tok < NTOK) ? 16u : 0u;
        int tc = tok < NTOK ? tok : NTOK - 1;
        size_t go = (size_t)(b * NTOK + tc) * (3 * DIMM) + h * HD + sg * 8;
        uint32_t so = (uint32_t)(r * AP + sg * 16);
        cp16(QH + so, qvh + go, sz);
        cp16(QL + so, qvl + go, sz);
    }

    auto issueK = [&](int t, int s) {
        int k0 = t * 64;
        #pragma unroll
        for (int i = 0; i < 2; i++) {
            int idx = tid + i * 256;
            int r = idx >> 3, sg = idx & 7;
            int tok = k0 + r;
            uint32_t sz = (tok < NTOK) ? 16u : 0u;
            int tc = tok < NTOK ? tok : NTOK - 1;
            size_t go = (size_t)(b * NTOK + tc) * (3 * DIMM) + DIMM + h * HD + sg * 8;
            uint32_t so = KST + s * 18432 + (uint32_t)(r * AP + sg * 16);
            cp16(so, qvh + go, sz);
            cp16(so + 9216, qvl + go, sz);
        }
        asm volatile("cp.async.commit_group;" ::: "memory");
    };

    issueK(0, 0);                   // group 0 = Q + K0
    issueK(1, 1);                   // group 1 = K1
    asm volatile("cp.async.wait_group 1;" ::: "memory");
    __syncthreads();

    const int lr = (lane & 7) + (lane & 8);
    const int lc = (lane & 16) ? 8 : 0;

    // preload Q fragments (persist across all k-tiles)
    uint32_t qfh[4][4], qfl[4][4];
    #pragma unroll
    for (int ks = 0; ks < 4; ks++) {
        uint32_t ao = (uint32_t)((wid * 16 + lr) * AP + (ks * 16 + lc) * 2);
        ldm_x4(QH + ao, qfh[ks]);
        ldm_x4(QL + ao, qfl[ks]);
    }

    const int r1 = q0 + wid * 16 + (lane >> 2);
    const int r2 = r1 + 8;
    float rs0 = 0.f, rs1 = 0.f;

    for (int t = 0; t < 10; t++) {
        const uint32_t KB = KST + (t & 1) * 18432;
        float acc[8][4];
        #pragma unroll
        for (int j = 0; j < 8; j++)
            #pragma unroll
            for (int q = 0; q < 4; q++) acc[j][q] = 0.f;

        #pragma unroll
        for (int ks = 0; ks < 4; ks++) {
            uint32_t kf[4][4];
            #pragma unroll
            for (int g = 0; g < 4; g++)
                ldm_x4(KB + (uint32_t)((g * 16 + lr) * AP + (ks * 16 + lc) * 2), kf[g]);
            #pragma unroll
            for (int nt = 0; nt < 8; nt++) {
                int g = nt >> 1, o = nt & 1;
                mma16816(acc[nt], qfh[ks], kf[g][o], kf[g][o + 2]);
            }
            #pragma unroll
            for (int nt = 0; nt < 8; nt++) {
                int g = nt >> 1, o = nt & 1;
                mma16816(acc[nt], qfl[ks], kf[g][o], kf[g][o + 2]);
            }
            #pragma unroll
            for (int g = 0; g < 4; g++)
                ldm_x4(KB + 9216 + (uint32_t)((g * 16 + lr) * AP + (ks * 16 + lc) * 2), kf[g]);
            #pragma unroll
            for (int nt = 0; nt < 8; nt++) {
                int g = nt >> 1, o = nt & 1;
                mma16816(acc[nt], qfh[ks], kf[g][o], kf[g][o + 2]);
            }
        }

        // exp + store P (zero for padded k) + accumulate row sums
        #pragma unroll
        for (int nt = 0; nt < 8; nt++) {
            int kcol = t * 64 + nt * 8 + (lane & 3) * 2;
            #pragma unroll
            for (int hh = 0; hh < 2; hh++) {
                float e0 = __expf(acc[nt][hh * 2]     * 0.125f);
                float e1 = __expf(acc[nt][hh * 2 + 1] * 0.125f);
                if (kcol     >= NTOK) e0 = 0.f;
                if (kcol + 1 >= NTOK) e1 = 0.f;
                if (hh == 0) rs0 += e0 + e1; else rs1 += e0 + e1;
                __nv_bfloat16 h0, l0, h1, l1;
                split_val(e0, h0, l0);
                split_val(e1, h1, l1);
                __nv_bfloat162 hv; hv.x = h0; hv.y = h1;
                __nv_bfloat162 lv; lv.x = l0; lv.y = l1;
                size_t o = ((size_t)bh * PQ + (hh ? r2 : r1)) * PQ + kcol;
                *(__nv_bfloat162*)(Ph + o) = hv;
                *(__nv_bfloat162*)(Pl + o) = lv;
            }
        }

        __syncthreads();
        if (t + 2 < 10) issueK(t + 2, t & 1);
        if (t + 1 < 10) {
            if (t + 2 < 10) asm volatile("cp.async.wait_group 1;" ::: "memory");
            else            asm volatile("cp.async.wait_group 0;" ::: "memory");
            __syncthreads();
        }
    }

    rs0 += __shfl_xor_sync(0xffffffffu, rs0, 1);
    rs0 += __shfl_xor_sync(0xffffffffu, rs0, 2);
    rs1 += __shfl_xor_sync(0xffffffffu, rs1, 1);
    rs1 += __shfl_xor_sync(0xffffffffu, rs1, 2);
    if ((lane & 3) == 0) {
        lsum[bh * PQ + r1] = rs0;
        lsum[bh * PQ + r2] = rs1;
    }
}

// ======================= attention: O = (P V) / l ===========================
#define AV_SMEM 110592

__global__ void __launch_bounds__(256) attn_avm(
    const __nv_bfloat16* __restrict__ qvh, const __nv_bfloat16* __restrict__ qvl,
    const __nv_bfloat16* __restrict__ Ph, const __nv_bfloat16* __restrict__ Pl,
    const float* __restrict__ lsum,
    __nv_bfloat16* __restrict__ Oh, __nv_bfloat16* __restrict__ Ol)
{
    extern __shared__ __align__(128) char smem[];
    const uint32_t sb = smem_u32(smem);
    const int tid = threadIdx.x, wid = tid >> 5, lane = tid & 31;
    const int qt = blockIdx.x, bh = blockIdx.y;
    const int b = bh / NHEAD, h = bh - b * NHEAD;
    const int q0 = qt * 128;

    auto issueT = [&](int t, int s) {
        const uint32_t ST = sb + s * 55296;
        int k0 = t * 64;
        #pragma unroll
        for (int i = 0; i < 4; i++) {
            int idx = tid + i * 256;
            int r = idx >> 3, sg = idx & 7;
            size_t go = ((size_t)bh * PQ + q0 + r) * PQ + k0 + sg * 8;
            uint32_t so = (uint32_t)(r * AP + sg * 16);
            cp16(ST + so,         Ph + go, 16u);
            cp16(ST + 18432 + so, Pl + go, 16u);
        }
        #pragma unroll
        for (int i = 0; i < 2; i++) {
            int idx = tid + i * 256;
            int r = idx >> 3, sg = idx & 7;
            int tok = k0 + r;
            uint32_t sz = (tok < NTOK) ? 16u : 0u;
            int tc = tok < NTOK ? tok : NTOK - 1;
            size_t go = (size_t)(b * NTOK + tc) * (3 * DIMM) + 2 * DIMM + h * HD + sg * 8;
            uint32_t so = (uint32_t)(r * AP + sg * 16);
            cp16(ST + 36864 + so, qvh + go, sz);
            cp16(ST + 46080 + so, qvl + go, sz);
        }
        asm volatile("cp.async.commit_group;" ::: "memory");
    };

    issueT(0, 0);
    issueT(1, 1);
    asm volatile("cp.async.wait_group 1;" ::: "memory");
    __syncthreads();

    const int lr = (lane & 7) + (lane & 8);
    const int lc = (lane & 16) ? 8 : 0;

    float acc[8][4];
    #pragma unroll
    for (int j = 0; j < 8; j++)
        #pragma unroll
        for (int q = 0; q < 4; q++) acc[j][q] = 0.f;

    for (int t = 0; t < 10; t++) {
        const uint32_t ST = sb + (t & 1) * 55296;
        #pragma unroll
        for (int ks = 0; ks < 4; ks++) {
            uint32_t pfh[4], pfl[4], vf[4][4];
            uint32_t ao = (uint32_t)((wid * 16 + lr) * AP + (ks * 16 + lc) * 2);
            ldm_x4(ST + ao,         pfh);
            ldm_x4(ST + 18432 + ao, pfl);
            #pragma unroll
            for (int g = 0; g < 4; g++)
                ldm_x4_t(ST + 36864 + (uint32_t)((ks * 16 + lr) * AP + (g * 16 + lc) * 2), vf[g]);
            #pragma unroll
            for (int nt = 0; nt < 8; nt++) {
                int g = nt >> 1, o = nt & 1;
                mma16816(acc[nt], pfh, vf[g][o * 2], vf[g][o * 2 + 1]);
            }
            #pragma unroll
            for (int nt = 0; nt < 8; nt++) {
                int g = nt >> 1, o = nt & 1;
                mma16816(acc[nt], pfl, vf[g][o * 2], vf[g][o * 2 + 1]);
            }
            #pragma unroll
            for (int g = 0; g < 4; g++)
                ldm_x4_t(ST + 46080 + (uint32_t)((ks * 16 + lr) * AP + (g * 16 + lc) * 2), vf[g]);
            #pragma unroll
            for (int nt = 0; nt < 8; nt++) {
                int g = nt >> 1, o = nt & 1;
                mma16816(acc[nt], pfh, vf[g][o * 2], vf[g][o * 2 + 1]);
            }
        }
        __syncthreads();
        if (t + 2 < 10) issueT(t + 2, t & 1);
        if (t + 1 < 10) {
            if (t + 2 < 10) asm volatile("cp.async.wait_group 1;" ::: "memory");
            else            asm volatile("cp.async.wait_group 0;" ::: "memory");
            __syncthreads();
        }
    }

    const int r1 = q0 + wid * 16 + (lane >> 2);
    const int r2 = r1 + 8;
    float inv1 = (r1 < NTOK) ? 1.f / lsum[bh * PQ + r1] : 0.f;
    float inv2 = (r2 < NTOK) ? 1.f / lsum[bh * PQ + r2] : 0.f;
    #pragma unroll
    for (int nt = 0; nt < 8; nt++) {
        int d = nt * 8 + (lane & 3) * 2;
        #pragma unroll
        for (int hh = 0; hh < 2; hh++) {
            int r = hh ? r2 : r1;
            if (r >= NTOK) continue;
            float inv = hh ? inv2 : inv1;
            float v0 = acc[nt][hh * 2]     * inv;
            float v1 = acc[nt][hh * 2 + 1] * inv;
            __nv_bfloat16 h0, l0, h1, l1;
            split_val(v0, h0, l0);
            split_val(v1, h1, l1);
            __nv_bfloat162 hv; hv.x = h0; hv.y = h1;
            __nv_bfloat162 lv; lv.x = l0; lv.y = l1;
            size_t o = (size_t)(b * NTOK + r) * DIMM + h * HD + d;
            *(__nv_bfloat162*)(Oh + o) = hv;
            *(__nv_bfloat162*)(Ol + o) = lv;
        }
    }
}

// ======================= fp32 GEMM (head only) ==============================
__global__ void __launch_bounds__(256) gemm_f32(
    const float* __restrict__ A, const float* __restrict__ Bm,
    const float* __restrict__ bias, float* __restrict__ C, int M, int N, int K)
{
    __shared__ float As[16][132];
    __shared__ float Bs[16][132];
    int tid = threadIdx.x;
    int m0 = blockIdx.y * 128, n0 = blockIdx.x * 128;
    int ty = tid >> 4, tx = tid & 15;
    float acc[8][8] = {};
    for (int k0 = 0; k0 < K; k0 += 16) {
        #pragma unroll
        for (int s = 0; s < 2; s++) {
            int idx = tid + s * 256;
            int r = idx >> 2, kq = idx & 3;
            float4 v = make_float4(0.f, 0.f, 0.f, 0.f);
            if (m0 + r < M)
                v = *(const float4*)(A + (size_t)(m0 + r) * K + k0 + kq * 4);
            As[kq * 4 + 0][r] = v.x; As[kq * 4 + 1][r] = v.y;
            As[kq * 4 + 2][r] = v.z; As[kq * 4 + 3][r] = v.w;
        }
        #pragma unroll
        for (int s = 0; s < 2; s++) {
            int idx = tid + s * 256;
            int r = idx >> 5, nq = idx & 31;
            float4 v = make_float4(0.f, 0.f, 0.f, 0.f);
            if (n0 + nq * 4 < N)
                v = *(const float4*)(Bm + (size_t)(k0 + r) * N + n0 + nq * 4);
            *(float4*)&Bs[r][nq * 4] = v;
        }
        __syncthreads();
        #pragma unroll
        for (int kk = 0; kk < 16; kk++) {
            float4 a0 = *(float4*)&As[kk][ty * 8];
            float4 a1 = *(float4*)&As[kk][ty * 8 + 4];
            float4 b0 = *(float4*)&Bs[kk][tx * 8];
            float4 b1 = *(float4*)&Bs[kk][tx * 8 + 4];
            float ar[8] = {a0.x, a0.y, a0.z, a0.w, a1.x, a1.y, a1.z, a1.w};
            float br[8] = {b0.x, b0.y, b0.z, b0.w, b1.x, b1.y, b1.z, b1.w};
            #pragma unroll
            for (int i = 0; i < 8; i++)
                #pragma unroll
                for (int j = 0; j < 8; j++)
                    acc[i][j] = fmaf(ar[i], br[j], acc[i][j]);
        }
        __syncthreads();
    }
    #pragma unroll
    for (int i = 0; i < 8; i++) {
        int m = m0 + ty * 8 + i;
        if (m >= M) continue;
        #pragma unroll
        for (int j = 0; j < 8; j++) {
            int n = n0 + tx * 8 + j;
            if (n < N) C[(size_t)m * N + n] = acc[i][j] + bias[n];
        }
    }
}

// ======================= host driver ========================================
extern "C" void kernel_launch(void* const* d_in, const int* in_sizes, int n_in,
                              void* d_out, int out_size)
{
    const float* x       = (const float*)d_in[0];
    const float* patch_w = (const float*)d_in[1];
    const float* patch_b = (const float*)d_in[2];
    const float* cls_t   = (const float*)d_in[3];
    const float* pos     = (const float*)d_in[4];
    const float* ln1_g   = (const float*)d_in[5];
    const float* ln1_b   = (const float*)d_in[6];
    const float* qkv_w   = (const float*)d_in[7];
    const float* qkv_b   = (const float*)d_in[8];
    const float* proj_w  = (const float*)d_in[9];
    const float* proj_b  = (const float*)d_in[10];
    const float* ln2_g   = (const float*)d_in[11];
    const float* ln2_b   = (const float*)d_in[12];
    const float* w1      = (const float*)d_in[13];
    const float* b1      = (const float*)d_in[14];
    const float* w2      = (const float*)d_in[15];
    const float* b2      = (const float*)d_in[16];
    const float* lnf_g   = (const float*)d_in[17];
    const float* lnf_b   = (const float*)d_in[18];
    const float* head_w  = (const float*)d_in[19];
    const float* head_b  = (const float*)d_in[20];
    float* out = (float*)d_out;

    cudaFuncSetAttribute(mma_gemm<0>, cudaFuncAttributeMaxDynamicSharedMemorySize, MM_SMEM);
    cudaFuncSetAttribute(mma_gemm<1>, cudaFuncAttributeMaxDynamicSharedMemorySize, MM_SMEM);
    cudaFuncSetAttribute(mma_gemm<2>, cudaFuncAttributeMaxDynamicSharedMemorySize, MM_SMEM);
    cudaFuncSetAttribute(mma_gemm<3>, cudaFuncAttributeMaxDynamicSharedMemorySize, MM_SMEM);
    cudaFuncSetAttribute(attn_pexp,   cudaFuncAttributeMaxDynamicSharedMemorySize, SC_SMEM);
    cudaFuncSetAttribute(attn_avm,    cudaFuncAttributeMaxDynamicSharedMemorySize, AV_SMEM);

    float *h, *hp, *cls, *lsum;
    cudaGetSymbolAddress((void**)&h,    g_h);
    cudaGetSymbolAddress((void**)&hp,   g_hp);
    cudaGetSymbolAddress((void**)&cls,  g_cls);
    cudaGetSymbolAddress((void**)&lsum, g_l);
    __nv_bfloat16 *yh, *yl, *qvh, *qvl, *Pph, *Ppl, *ath, *atl, *mh, *ml, *pph, *ppl, *pwh, *pwl;
    __nv_bfloat16 *qTh, *qTl, *pTh, *pTl, *w1h, *w1l, *w2h, *w2l;
    cudaGetSymbolAddress((void**)&yh,  g_yh);    cudaGetSymbolAddress((void**)&yl,  g_yl);
    cudaGetSymbolAddress((void**)&qvh, g_qkvh);  cudaGetSymbolAddress((void**)&qvl, g_qkvl);
    cudaGetSymbolAddress((void**)&Pph, g_Ph);    cudaGetSymbolAddress((void**)&Ppl, g_Pl);
    cudaGetSymbolAddress((void**)&ath, g_ath);   cudaGetSymbolAddress((void**)&atl, g_atl);
    cudaGetSymbolAddress((void**)&mh,  g_mh);    cudaGetSymbolAddress((void**)&ml,  g_ml);
    cudaGetSymbolAddress((void**)&pph, g_ph);    cudaGetSymbolAddress((void**)&ppl, g_pl);
    cudaGetSymbolAddress((void**)&pwh, g_pwh);   cudaGetSymbolAddress((void**)&pwl, g_pwl);
    cudaGetSymbolAddress((void**)&qTh, g_qkvTh); cudaGetSymbolAddress((void**)&qTl, g_qkvTl);
    cudaGetSymbolAddress((void**)&pTh, g_projTh);cudaGetSymbolAddress((void**)&pTl, g_projTl);
    cudaGetSymbolAddress((void**)&w1h, g_w1Th);  cudaGetSymbolAddress((void**)&w1l, g_w1Tl);
    cudaGetSymbolAddress((void**)&w2h, g_w2Th);  cudaGetSymbolAddress((void**)&w2l, g_w2Tl);

    dim3 t328(32, 8);
    split_planes<<<(DIMM * DIMM + 255) / 256, 256>>>(patch_w, pwh, pwl, DIMM * DIMM);
    tr_split<<<dim3(72, 24, DEPTH), t328>>>(qkv_w,  qTh, qTl, DIMM, 3 * DIMM);
    tr_split<<<dim3(24, 24, DEPTH), t328>>>(proj_w, pTh, pTl, DIMM, DIMM);
    tr_split<<<dim3(96, 24, DEPTH), t328>>>(w1,     w1h, w1l, DIMM, HID);
    tr_split<<<dim3(24, 96, DEPTH), t328>>>(w2,     w2h, w2l, HID, DIMM);

    patch_extract<<<(BATCH * NPATCH * DIMM + 255) / 256, 256>>>(x, pph, ppl);
    mma_gemm<0><<<dim3(6, 36), 256, MM_SMEM>>>(pph, ppl, pwh, pwl, patch_b, nullptr,
                                               hp, nullptr, nullptr,
                                               BATCH * NPATCH, DIMM, DIMM);
    add_pos_cls<<<TOKS, 256>>>(hp, cls_t, pos, h);

    for (int l = 0; l < DEPTH; l++) {
        ln_kernel<1><<<TOKS, 256>>>(h, ln1_g + l * DIMM, ln1_b + l * DIMM,
                                    nullptr, yh, yl, 1e-5f, DIMM);
        mma_gemm<3><<<dim3(18, 37), 256, MM_SMEM>>>(
            yh, yl, qTh + (size_t)l * 3 * DIMM * DIMM, qTl + (size_t)l * 3 * DIMM * DIMM,
            qkv_b + l * 3 * DIMM, nullptr, nullptr, qvh, qvl, TOKS, 3 * DIMM, DIMM);
        attn_pexp<<<dim3(5, BH), 256, SC_SMEM>>>(qvh, qvl, Pph, Ppl, lsum);
        attn_avm<<<dim3(5, BH), 256, AV_SMEM>>>(qvh, qvl, Pph, Ppl, lsum, ath, atl);
        mma_gemm<2><<<dim3(6, 37), 256, MM_SMEM>>>(
            ath, atl, pTh + (size_t)l * DIMM * DIMM, pTl + (size_t)l * DIMM * DIMM,
            proj_b + l * DIMM, h, h, nullptr, nullptr, TOKS, DIMM, DIMM);
        ln_kernel<1><<<TOKS, 256>>>(h, ln2_g + l * DIMM, ln2_b + l * DIMM,
                                    nullptr, yh, yl, 1e-5f, DIMM);
        mma_gemm<1><<<dim3(24, 37), 256, MM_SMEM>>>(
            yh, yl, w1h + (size_t)l * HID * DIMM, w1l + (size_t)l * HID * DIMM,
            b1 + l * HID, nullptr, nullptr, mh, ml, TOKS, HID, DIMM);
        mma_gemm<2><<<dim3(6, 37), 256, MM_SMEM>>>(
            mh, ml, w2h + (size_t)l * DIMM * HID, w2l + (size_t)l * DIMM * HID,
            b2 + l * DIMM, h, h, nullptr, nullptr, TOKS, DIMM, HID);
    }

    ln_kernel<0><<<BATCH, 256>>>(h, lnf_g, lnf_b, cls, nullptr, nullptr,
                                 1e-6f, (long)NTOK * DIMM);
    gemm_f32<<<dim3(8, 1), 256>>>(cls, head_w, head_b, out, BATCH, 1000, DIMM);
}